// round 5
// baseline (speedup 1.0000x reference)
#include <cuda_runtime.h>
#include <cuda_bf16.h>
#include <cstdint>

// Volume rendering composite.
// Inputs: depth [N,192,1] f32, rgb [N,192,3] f32, sigma [N,192,1] f32
// Output (concat, f32): color [N,3], depth_out [N,1], acc_map [N,1], weights [N,192,1]
//
// One warp per ray; lane l owns samples [6l, 6l+6).
// Phase 1: depth+sigma loads -> survival -> single warp scan -> weights + dacc.
// Phase 2: rgb streamed in 3 chunks of 2 samples, HW-tanh sigmoid, accumulate.
// Register budget capped at 32 (launch_bounds 256,8) for full occupancy.

#define NRAYS 65536
#define NSAMP 192

__device__ __forceinline__ float ex2_approx(float x) {
    float r;
    asm("ex2.approx.f32 %0, %1;" : "=f"(r) : "f"(x));
    return r;
}
__device__ __forceinline__ float tanh_approx(float x) {
    float r;
    asm("tanh.approx.f32 %0, %1;" : "=f"(r) : "f"(x));
    return r;
}
// sigmoid(x) = 0.5 * tanh(x/2) + 0.5  -- one MUFU op
__device__ __forceinline__ float sigmoid_fast(float x) {
    return fmaf(0.5f, tanh_approx(0.5f * x), 0.5f);
}

__global__ void __launch_bounds__(256, 8)
volrend_kernel(const float* __restrict__ depth,
               const float* __restrict__ rgb,
               const float* __restrict__ sigma,
               float* __restrict__ out)
{
    const int gwarp = (blockIdx.x * blockDim.x + threadIdx.x) >> 5;
    const int lane  = threadIdx.x & 31;
    const int ray   = gwarp;

    const float* __restrict__ dptr = depth + (size_t)ray * NSAMP + 6 * lane;
    const float* __restrict__ sptr = sigma + (size_t)ray * NSAMP + 6 * lane;

    const float BOARDER = 1e10f;
    const float EPS     = 1e-10f;
    const float LOG2E   = 1.4426950408889634f;

    // ---- phase-1 loads: depth + sigma (streaming, coalesced, vectorized) ----
    const float2 d01 = __ldcs((const float2*)(dptr + 0));
    const float2 d23 = __ldcs((const float2*)(dptr + 2));
    const float2 d45 = __ldcs((const float2*)(dptr + 4));
    const float2 g01 = __ldcs((const float2*)(sptr + 0));
    const float2 g23 = __ldcs((const float2*)(sptr + 2));
    const float2 g45 = __ldcs((const float2*)(sptr + 4));

    float d[6] = { d01.x, d01.y, d23.x, d23.y, d45.x, d45.y };
    float g[6] = { g01.x, g01.y, g23.x, g23.y, g45.x, g45.y };

    // ---- deltas (neighbor's first depth via one shuffle) ----
    const float dnext = __shfl_down_sync(0xffffffffu, d[0], 1);
    const float delta5 = (lane == 31) ? BOARDER : (dnext - d[5]);

    // ---- survival probs ----
    float surv[6];
    #pragma unroll
    for (int j = 0; j < 6; ++j) {
        const float dl = (j < 5) ? (d[j + 1] - d[j]) : delta5;
        const float x  = fmaxf(g[j], 0.0f) * dl;
        surv[j] = ex2_approx(-x * LOG2E) + EPS;
    }

    // ---- local exclusive prefix products (Q[0]=1 implicit) ----
    float Q[6];
    Q[0] = 1.0f;
    #pragma unroll
    for (int j = 1; j < 6; ++j) Q[j] = Q[j - 1] * surv[j - 1];
    const float ploc = Q[5] * surv[5];

    // ---- single 5-step warp scan over per-lane products ----
    float incl = ploc;
    #pragma unroll
    for (int off = 1; off < 32; off <<= 1) {
        const float v = __shfl_up_sync(0xffffffffu, incl, off);
        if (lane >= off) incl *= v;
    }
    float excl = __shfl_up_sync(0xffffffffu, incl, 1);
    if (lane == 0) excl = 1.0f;

    // ---- weights + depth accumulation (frees d, surv, Q) ----
    float w[6];
    float dacc = 0.f, aacc = 0.f;
    #pragma unroll
    for (int j = 0; j < 6; ++j) {
        w[j]  = (1.0f - surv[j] + EPS) * (excl * Q[j]);
        dacc  = fmaf(w[j], d[j], dacc);
        aacc += w[j];
    }

    // ---- store weights (streaming, coalesced) ----
    float* __restrict__ w_out = out + (size_t)NRAYS * 5
                                    + (size_t)ray * NSAMP + 6 * lane;
    __stcs((float2*)(w_out + 0), make_float2(w[0], w[1]));
    __stcs((float2*)(w_out + 2), make_float2(w[2], w[3]));
    __stcs((float2*)(w_out + 4), make_float2(w[4], w[5]));

    // ---- phase 2: rgb streamed in 3 chunks of 2 samples (6 floats) ----
    const float2* __restrict__ rptr =
        (const float2*)(rgb + (size_t)ray * NSAMP * 3 + 18 * lane);

    float c0 = 0.f, c1 = 0.f, c2 = 0.f;
    #pragma unroll
    for (int c = 0; c < 3; ++c) {
        const float2 a = __ldcs(rptr + 3 * c + 0);
        const float2 b = __ldcs(rptr + 3 * c + 1);
        const float2 e = __ldcs(rptr + 3 * c + 2);
        const float wA = w[2 * c + 0];
        const float wB = w[2 * c + 1];
        c0 = fmaf(wA, sigmoid_fast(a.x), c0);
        c1 = fmaf(wA, sigmoid_fast(a.y), c1);
        c2 = fmaf(wA, sigmoid_fast(b.x), c2);
        c0 = fmaf(wB, sigmoid_fast(b.y), c0);
        c1 = fmaf(wB, sigmoid_fast(e.x), c1);
        c2 = fmaf(wB, sigmoid_fast(e.y), c2);
    }

    // ---- warp reduction ----
    #pragma unroll
    for (int off = 16; off > 0; off >>= 1) {
        c0   += __shfl_down_sync(0xffffffffu, c0,   off);
        c1   += __shfl_down_sync(0xffffffffu, c1,   off);
        c2   += __shfl_down_sync(0xffffffffu, c2,   off);
        dacc += __shfl_down_sync(0xffffffffu, dacc, off);
        aacc += __shfl_down_sync(0xffffffffu, aacc, off);
    }
    if (lane == 0) {
        out[3 * ray + 0] = c0;
        out[3 * ray + 1] = c1;
        out[3 * ray + 2] = c2;
        out[(size_t)NRAYS * 3 + ray] = dacc;
        out[(size_t)NRAYS * 4 + ray] = aacc;
    }
}

extern "C" void kernel_launch(void* const* d_in, const int* in_sizes, int n_in,
                              void* d_out, int out_size)
{
    const float* depth = (const float*)d_in[0];
    const float* rgb   = (const float*)d_in[1];
    const float* sigma = (const float*)d_in[2];
    float* out = (float*)d_out;

    const int threads = 256;                    // 8 warps/block
    const int blocks  = NRAYS / (threads / 32); // 8192
    volrend_kernel<<<blocks, threads>>>(depth, rgb, sigma, out);
}